// round 13
// baseline (speedup 1.0000x reference)
#include <cuda_runtime.h>
#include <cuda_fp16.h>
#include <cstdint>

// ---------------------------------------------------------------------------
// Problem constants
// ---------------------------------------------------------------------------
#define BATCH 4096
#define NDIM  64
#define FDIM  4096
#define KP    2080          // N*(N+1)/2
#define KPAD  2112          // KP padded (66 chunks of 32)
#define EMB_ELEMS (4096u*4096u)
#define NCHUNK (KPAD/32)    // 66

// Prep kernel partition (kp_pair + W conversion; copy lives in the GEMM grid)
#define KP_BLOCKS    2048                       // 2 batches per block
#define CONV_BLOCKS  16640                      // 2*4096*520 quads / 256
#define PREP_BLOCKS  (KP_BLOCKS + CONV_BLOCKS)

// GEMM grid: 1024 gemm CTAs + 1024 copy CTAs
#define GEMM_BLOCKS  1024
#define COPYG_BLOCKS 1024                       // 4M float4 / (512 thr * 8)

// fp16 operand planes. Rows [0,4096) = view0 (triu / W_triu), [4096,8192) = view1.
// Pad cols [2080,2112) stay zero (.bss zero-init, never written).
__device__ __align__(1024) __half g_A [(size_t)8192 * KPAD];
__device__ __align__(1024) __half g_Wc[(size_t)8192 * KPAD];

// ---------------------------------------------------------------------------
// Small helpers
// ---------------------------------------------------------------------------
__device__ __forceinline__ uint32_t smem_to_u32(const void* p) {
    uint32_t a;
    asm("{ .reg .u64 t; cvta.to.shared.u64 t, %1; cvt.u32.u64 %0, t; }"
        : "=r"(a) : "l"(p));
    return a;
}

__device__ __forceinline__ uint32_t h2_as_u32(__half2 h) {
    uint32_t u;
    __builtin_memcpy(&u, &h, 4);
    return u;
}

__device__ __forceinline__ void cp16(uint32_t dst, const void* src) {
    asm volatile("cp.async.cg.shared.global [%0], [%1], 16;"
                 :: "r"(dst), "l"(src));
}
#define CP_COMMIT() asm volatile("cp.async.commit_group;" ::: "memory")
#define CP_WAIT3()  asm volatile("cp.async.wait_group 3;" ::: "memory")

__device__ __forceinline__ void ldsm4(uint32_t (&r)[4], uint32_t addr) {
    asm volatile("ldmatrix.sync.aligned.m8n8.x4.shared.b16 {%0,%1,%2,%3}, [%4];"
                 : "=r"(r[0]), "=r"(r[1]), "=r"(r[2]), "=r"(r[3]) : "r"(addr));
}

__device__ __forceinline__ void mma_fp16(float (&d)[4], const uint32_t (&a)[4],
                                         uint32_t b0, uint32_t b1) {
    asm volatile(
        "mma.sync.aligned.m16n8k16.row.col.f32.f16.f16.f32 "
        "{%0,%1,%2,%3}, {%4,%5,%6,%7}, {%8,%9}, {%0,%1,%2,%3};"
        : "+f"(d[0]), "+f"(d[1]), "+f"(d[2]), "+f"(d[3])
        : "r"(a[0]), "r"(a[1]), "r"(a[2]), "r"(a[3]), "r"(b0), "r"(b1));
}

// XOR swizzle for 64B rows (GEMM stage planes): row r, 16B-chunk c (0..3).
__device__ __forceinline__ uint32_t swz(uint32_t r, uint32_t c) {
    return (r * 4u + (c ^ ((r >> 1) & 3u))) * 16u;
}

// Full SW128 XOR swizzle for 128B rows (kp_pair tiles): row r, chunk c (0..7).
__device__ __forceinline__ uint32_t swz128(uint32_t r, uint32_t c) {
    return r * 128u + ((c ^ (r & 7u)) << 4);
}

// ---------------------------------------------------------------------------
// kp_pair body: TWO batches per block (b0 and b0+2048); kpW loaded to smem
// once and reused. embs_kp = F @ kpW @ F^T via mma.sync, scatter triu/tril
// as fp16 into g_A. 256 threads = 8 warps.
// ---------------------------------------------------------------------------
__device__ void kp_pair_body2(int b0, const float* __restrict__ femb,
                              const float* __restrict__ kpW)
{
    __shared__ __align__(128) __half Fh[64 * 64];  // F,  swizzled 128B rows
    __shared__ __align__(128) __half Wt[64 * 64];  // kpW^T, swizzled (persists)
    __shared__ __align__(128) __half Th[64 * 64];  // T = F@kpW, swizzled

    const uint32_t sF = smem_to_u32(Fh);
    const uint32_t sW = smem_to_u32(Wt);
    const uint32_t sT = smem_to_u32(Th);

    const int tid  = threadIdx.x;
    const int lane = tid & 31;
    const int w    = tid >> 5;

    // Load kpW (fp32) transposed -> fp16 swizzled smem ONCE. 16 scalars/thread.
    #pragma unroll
    for (int k = 0; k < 16; k++) {
        const int idx = tid + k * 256;
        const int d = idx >> 6, e = idx & 63;
        const __half h = __float2half_rn(kpW[idx]);
        const int c = d >> 3;
        *(__half*)((char*)Wt + swz128(e, c) + (d & 7) * 2) = h;
    }

    const int mt = (w & 3) * 16;          // output row tile
    const int nb = (w >> 2) * 32;         // output col base
    const uint32_t a_r    = mt + (lane & 15);
    const uint32_t a_csel = (uint32_t)(lane >> 4);
    const uint32_t b_rb   = nb + ((lane >> 4) << 3) + (lane & 7);
    const uint32_t b_csel = (uint32_t)((lane >> 3) & 1);

    #pragma unroll
    for (int it = 0; it < 2; it++) {
        const int b = b0 + it * 2048;
        const float* Fb = femb + (size_t)b * (NDIM * NDIM);

        // Load F (fp32) -> fp16 swizzled smem (2 chunks of 8 halves/thread)
        {
            const int r  = tid >> 2;
            const int c0 = (tid & 3) * 2;
            #pragma unroll
            for (int cc = 0; cc < 2; cc++) {
                const int c = c0 + cc;
                float4 x0 = *(const float4*)(Fb + r * 64 + c * 8);
                float4 x1 = *(const float4*)(Fb + r * 64 + c * 8 + 4);
                uint4 pk;
                pk.x = h2_as_u32(__floats2half2_rn(x0.x, x0.y));
                pk.y = h2_as_u32(__floats2half2_rn(x0.z, x0.w));
                pk.z = h2_as_u32(__floats2half2_rn(x1.x, x1.y));
                pk.w = h2_as_u32(__floats2half2_rn(x1.z, x1.w));
                *(uint4*)((char*)Fh + swz128(r, c)) = pk;
            }
        }
        __syncthreads();

        // GEMM1: T = F @ kpW
        float acc1[4][4] = {};
        #pragma unroll
        for (int ks = 0; ks < 4; ks++) {
            uint32_t a_f[4];
            ldsm4(a_f, sF + swz128(a_r, ks * 2 + a_csel));
            uint32_t b_f[2][4];
            #pragma unroll
            for (int j = 0; j < 2; j++)
                ldsm4(b_f[j], sW + swz128(b_rb + j * 16, ks * 2 + b_csel));
            #pragma unroll
            for (int ni = 0; ni < 4; ni++)
                mma_fp16(acc1[ni], a_f, b_f[ni >> 1][(ni & 1) * 2],
                         b_f[ni >> 1][(ni & 1) * 2 + 1]);
        }

        // Store T (fp16, swizzled)
        {
            const int tr = mt + (lane >> 2);
            #pragma unroll
            for (int ni = 0; ni < 4; ni++) {
                const int col = nb + ni * 8 + (lane & 3) * 2;
                const int c = col >> 3;
                *(__half2*)((char*)Th + swz128(tr, c) + (col & 7) * 2) =
                    __floats2half2_rn(acc1[ni][0], acc1[ni][1]);
                *(__half2*)((char*)Th + swz128(tr + 8, c) + (col & 7) * 2) =
                    __floats2half2_rn(acc1[ni][2], acc1[ni][3]);
            }
        }
        __syncthreads();

        // GEMM2: E = T @ F^T
        float acc2[4][4] = {};
        #pragma unroll
        for (int ks = 0; ks < 4; ks++) {
            uint32_t a_f[4];
            ldsm4(a_f, sT + swz128(a_r, ks * 2 + a_csel));
            uint32_t b_f[2][4];
            #pragma unroll
            for (int j = 0; j < 2; j++)
                ldsm4(b_f[j], sF + swz128(b_rb + j * 16, ks * 2 + b_csel));
            #pragma unroll
            for (int ni = 0; ni < 4; ni++)
                mma_fp16(acc2[ni], a_f, b_f[ni >> 1][(ni & 1) * 2],
                         b_f[ni >> 1][(ni & 1) * 2 + 1]);
        }

        // Scatter E into triu/tril fp16 planes
        __half* tri_row = g_A + (size_t)b * KPAD;            // view 0
        __half* trl_row = g_A + (size_t)(4096 + b) * KPAD;   // view 1
        const int rr = mt + (lane >> 2);
        #pragma unroll
        for (int ni = 0; ni < 4; ni++) {
            const int cb = nb + ni * 8 + (lane & 3) * 2;
            #pragma unroll
            for (int q = 0; q < 4; q++) {
                const int r = rr + (q >> 1) * 8;
                const int c = cb + (q & 1);
                const __half h = __float2half_rn(acc2[ni][q]);
                if (r <= c) tri_row[r * 64 - (r * (r - 1)) / 2 - r + c] = h;
                if (r >= c) trl_row[(r * (r + 1)) / 2 + c] = h;
            }
        }
        if (it == 0) __syncthreads();   // Fh/Th overwritten next iteration
    }
}

// ---------------------------------------------------------------------------
// Prep kernel: [0, KP_BLOCKS) kp_pair x2; remainder converts W planes.
// ---------------------------------------------------------------------------
__global__ __launch_bounds__(256) void prep_kernel(
    const float* __restrict__ femb, const float* __restrict__ kpW,
    const float* __restrict__ Wt, const float* __restrict__ Wl)
{
    const int bid = blockIdx.x;

    if (bid < KP_BLOCKS) {
        kp_pair_body2(bid, femb, kpW);
        return;
    }

    // Convert W_triu/W_tril fp32 -> fp16 plane in g_Wc
    const size_t idx = (size_t)(bid - KP_BLOCKS) * 256 + threadIdx.x;
    int v = (int)(idx / ((size_t)4096 * 520));
    size_t rem = idx - (size_t)v * 4096 * 520;
    int f = (int)(rem / 520), q = (int)(rem % 520);

    const float* W = v ? Wl : Wt;
    float4 x = reinterpret_cast<const float4*>(W + (size_t)f * KP)[q];

    __half* row = g_Wc + (size_t)(v * 4096 + f) * KPAD;
    __half2* o = reinterpret_cast<__half2*>(row + q * 4);
    o[0] = __floats2half2_rn(x.x, x.y);
    o[1] = __floats2half2_rn(x.z, x.w);
}

// ---------------------------------------------------------------------------
// Kernel B: mma.sync fp16 GEMM (fp32 accumulate), 512 threads = 16 warps.
// EXACT round-10 measured-best configuration:
// CTA tile 128(M) x 256(N), BK=32, warp grid 2M x 8N (warp tile 64x32),
// 5-stage cp.async pipeline (24KB/stage). Appended CTAs do the embs copy.
// ---------------------------------------------------------------------------
#define PL_A 0
#define PL_B 8192           // A plane 8KB, B plane 16KB
#define STAGE_BYTES 24576
#define NSTAGE 5
#define SMEM_GEMM (NSTAGE * STAGE_BYTES)

__global__ void __launch_bounds__(512, 1) void_marker();  // (unused fwd decl guard)

__global__ void __launch_bounds__(512, 1) view_gemm_kernel(
    float* __restrict__ out, const float* __restrict__ femb)
{
    // ---- appended copy CTAs: segment 0 (embs_flatten) ----
    if (blockIdx.x >= GEMM_BLOCKS) {
        const size_t base = (size_t)(blockIdx.x - GEMM_BLOCKS) * (512 * 8)
                          + threadIdx.x;
        #pragma unroll
        for (int i = 0; i < 8; i++) {
            const size_t q = base + (size_t)i * 512;
            reinterpret_cast<float4*>(out)[q] =
                reinterpret_cast<const float4*>(femb)[q];
        }
        return;
    }

    extern __shared__ char smem[];
    const uint32_t sb0 = smem_to_u32(smem);

    const int tid  = threadIdx.x;
    const int lane = tid & 31;
    const int wid  = tid >> 5;
    const int warpM = wid & 1;        // 0..1  (64 rows each)
    const int warpN = wid >> 1;       // 0..7  (32 cols each)

    const int id   = blockIdx.x;
    const int view = id >> 9;
    const int m0   = ((id >> 4) & 31) * 128;
    const int n0   = (id & 15) * 256;

    const __half* Abase = g_A  + (size_t)(view * 4096 + m0) * KPAD;
    const __half* Bbase = g_Wc + (size_t)(view * 4096 + n0) * KPAD;

    // cp.async: 3 x 16B per thread per stage (1 A chunk + 2 B chunks).
    const int lr = tid >> 2;           // 0..127
    const int lc = tid & 3;            // 16B chunk 0..3
    const __half* srcA  = Abase + (size_t)lr * KPAD + lc * 8;
    const __half* srcB0 = Bbase + (size_t)lr * KPAD + lc * 8;
    const __half* srcB1 = Bbase + (size_t)(lr + 128) * KPAD + lc * 8;
    const uint32_t soA  = PL_A + swz(lr, lc);
    const uint32_t soB0 = PL_B + swz(lr, lc);
    const uint32_t soB1 = PL_B + swz(lr + 128, lc);

    float acc[4][4][4] = {};

    // ---- pipeline prologue: stages 0..3 ----
    #pragma unroll
    for (int s = 0; s < 4; s++) {
        const uint32_t sb = sb0 + s * STAGE_BYTES;
        const size_t kb = (size_t)s * 32;
        cp16(sb + soA,  srcA  + kb);
        cp16(sb + soB0, srcB0 + kb);
        cp16(sb + soB1, srcB1 + kb);
        CP_COMMIT();
    }

    // ldmatrix lane-dependent address components
    const uint32_t a_r = warpM * 64 + (lane & 15);                   // + mi*16
    const uint32_t a_c = (uint32_t)(lane >> 4);                      // + ks*2
    const uint32_t b_r = warpN * 32 + (lane >> 4) * 8 + (lane & 7);  // + j*16
    const uint32_t b_c = (uint32_t)((lane >> 3) & 1);                // + ks*2

    int stage_c = 0;   // compute stage index (mod NSTAGE)
    int stage_l = 4;   // load stage index (mod NSTAGE)

    for (int ch = 0; ch < NCHUNK; ch++) {
        CP_WAIT3();
        __syncthreads();

        // issue loads for ch+4 (overwrites buffer of ch-1, already consumed)
        if (ch + 4 < NCHUNK) {
            const uint32_t sb = sb0 + stage_l * STAGE_BYTES;
            const size_t kb = (size_t)(ch + 4) * 32;
            cp16(sb + soA,  srcA  + kb);
            cp16(sb + soB0, srcB0 + kb);
            cp16(sb + soB1, srcB1 + kb);
        }
        CP_COMMIT();
        if (++stage_l == NSTAGE) stage_l = 0;

        const uint32_t sb = sb0 + stage_c * STAGE_BYTES;
        if (++stage_c == NSTAGE) stage_c = 0;

        #pragma unroll
        for (int ks = 0; ks < 2; ks++) {
            uint32_t b_f[2][4];
            #pragma unroll
            for (int j = 0; j < 2; j++) {
                const uint32_t off = swz(b_r + j * 16, b_c + ks * 2);
                ldsm4(b_f[j], sb + PL_B + off);
            }
            uint32_t a_f[4][4];
            #pragma unroll
            for (int mi = 0; mi < 4; mi++) {
                const uint32_t off = swz(a_r + mi * 16, a_c + ks * 2);
                ldsm4(a_f[mi], sb + PL_A + off);
            }
            #pragma unroll
            for (int mi = 0; mi < 4; mi++) {
                #pragma unroll
                for (int ni = 0; ni < 4; ni++) {
                    const int j = ni >> 1, h = (ni & 1) * 2;
                    mma_fp16(acc[mi][ni], a_f[mi], b_f[j][h], b_f[j][h + 1]);
                }
            }
        }
    }

    // ---- epilogue: direct float2 stores ----
    float* C = out + (size_t)(1 + view) * EMB_ELEMS;
    const int rbase = m0 + warpM * 64 + (lane >> 2);
    const int cbase = n0 + warpN * 32 + (lane & 3) * 2;
    #pragma unroll
    for (int mi = 0; mi < 4; mi++) {
        #pragma unroll
        for (int ni = 0; ni < 4; ni++) {
            const size_t r0 = (size_t)(rbase + mi * 16);
            const int cc = cbase + ni * 8;
            *reinterpret_cast<float2*>(&C[r0 * FDIM + cc]) =
                make_float2(acc[mi][ni][0], acc[mi][ni][1]);
            *reinterpret_cast<float2*>(&C[(r0 + 8) * FDIM + cc]) =
                make_float2(acc[mi][ni][2], acc[mi][ni][3]);
        }
    }
}

// ---------------------------------------------------------------------------
// Host launch
// Inputs: feature_emb, kp_W, W_triu, W_tril (all fp32)
// Output: [embs_flatten | view_1 | view_2], each 4096*4096 fp32.
// ---------------------------------------------------------------------------
extern "C" void kernel_launch(void* const* d_in, const int* in_sizes, int n_in,
                              void* d_out, int out_size)
{
    const float* femb   = (const float*)d_in[0];
    const float* kpW    = (const float*)d_in[1];
    const float* W_triu = (const float*)d_in[2];
    const float* W_tril = (const float*)d_in[3];
    float* out = (float*)d_out;

    // Prep: kp_pair (2 batches/block) + W conversion (one launch)
    prep_kernel<<<PREP_BLOCKS, 256>>>(femb, kpW, W_triu, W_tril);

    // GEMMs + embs_flatten copy in one grid
    cudaFuncSetAttribute(view_gemm_kernel,
                         cudaFuncAttributeMaxDynamicSharedMemorySize, SMEM_GEMM);
    view_gemm_kernel<<<GEMM_BLOCKS + COPYG_BLOCKS, 512, SMEM_GEMM>>>(out, femb);
}

// round 14
// speedup vs baseline: 1.0942x; 1.0942x over previous
#include <cuda_runtime.h>
#include <cuda_fp16.h>
#include <cstdint>

// ---------------------------------------------------------------------------
// Problem constants
// ---------------------------------------------------------------------------
#define BATCH 4096
#define NDIM  64
#define FDIM  4096
#define KP    2080          // N*(N+1)/2
#define KPAD  2112          // KP padded (66 chunks of 32)
#define EMB_ELEMS (4096u*4096u)
#define NCHUNK (KPAD/32)    // 66

// Prep kernel partition (kp_pair + W conversion; copy lives in the GEMM grid)
#define KP_BLOCKS    4096                       // 1 batch per block (round-10)
#define CONV_BLOCKS  2080                       // 2*4096*520 quads / (256*8)
#define PREP_BLOCKS  (KP_BLOCKS + CONV_BLOCKS)

// GEMM grid: 1024 gemm CTAs + 1024 copy CTAs
#define GEMM_BLOCKS  1024
#define COPYG_BLOCKS 1024                       // 4M float4 / (512 thr * 8)

// fp16 operand planes. Rows [0,4096) = view0 (triu / W_triu), [4096,8192) = view1.
// Pad cols [2080,2112) stay zero (.bss zero-init, never written).
__device__ __align__(1024) __half g_A [(size_t)8192 * KPAD];
__device__ __align__(1024) __half g_Wc[(size_t)8192 * KPAD];

// ---------------------------------------------------------------------------
// Small helpers
// ---------------------------------------------------------------------------
__device__ __forceinline__ uint32_t smem_to_u32(const void* p) {
    uint32_t a;
    asm("{ .reg .u64 t; cvta.to.shared.u64 t, %1; cvt.u32.u64 %0, t; }"
        : "=r"(a) : "l"(p));
    return a;
}

__device__ __forceinline__ uint32_t h2_as_u32(__half2 h) {
    uint32_t u;
    __builtin_memcpy(&u, &h, 4);
    return u;
}

__device__ __forceinline__ void cp16(uint32_t dst, const void* src) {
    asm volatile("cp.async.cg.shared.global [%0], [%1], 16;"
                 :: "r"(dst), "l"(src));
}
#define CP_COMMIT() asm volatile("cp.async.commit_group;" ::: "memory")
#define CP_WAIT3()  asm volatile("cp.async.wait_group 3;" ::: "memory")

__device__ __forceinline__ void ldsm4(uint32_t (&r)[4], uint32_t addr) {
    asm volatile("ldmatrix.sync.aligned.m8n8.x4.shared.b16 {%0,%1,%2,%3}, [%4];"
                 : "=r"(r[0]), "=r"(r[1]), "=r"(r[2]), "=r"(r[3]) : "r"(addr));
}

__device__ __forceinline__ void mma_fp16(float (&d)[4], const uint32_t (&a)[4],
                                         uint32_t b0, uint32_t b1) {
    asm volatile(
        "mma.sync.aligned.m16n8k16.row.col.f32.f16.f16.f32 "
        "{%0,%1,%2,%3}, {%4,%5,%6,%7}, {%8,%9}, {%0,%1,%2,%3};"
        : "+f"(d[0]), "+f"(d[1]), "+f"(d[2]), "+f"(d[3])
        : "r"(a[0]), "r"(a[1]), "r"(a[2]), "r"(a[3]), "r"(b0), "r"(b1));
}

// XOR swizzle for 64B rows (GEMM stage planes): row r, 16B-chunk c (0..3).
__device__ __forceinline__ uint32_t swz(uint32_t r, uint32_t c) {
    return (r * 4u + (c ^ ((r >> 1) & 3u))) * 16u;
}

// Full SW128 XOR swizzle for 128B rows (kp_pair tiles): row r, chunk c (0..7).
__device__ __forceinline__ uint32_t swz128(uint32_t r, uint32_t c) {
    return r * 128u + ((c ^ (r & 7u)) << 4);
}

// ---------------------------------------------------------------------------
// kp_pair body (round-10 exact): per-batch embs_kp = F @ kpW @ F^T via
// mma.sync, scatter triu/tril as fp16 into g_A. 256 threads = 8 warps.
// ---------------------------------------------------------------------------
__device__ void kp_pair_body(int b, const float* __restrict__ femb,
                             const float* __restrict__ kpW)
{
    __shared__ __align__(128) __half Fh[64 * 64];  // F,  swizzled 128B rows
    __shared__ __align__(128) __half Wt[64 * 64];  // kpW^T, swizzled
    __shared__ __align__(128) __half Th[64 * 64];  // T = F@kpW, swizzled

    const uint32_t sF = smem_to_u32(Fh);
    const uint32_t sW = smem_to_u32(Wt);
    const uint32_t sT = smem_to_u32(Th);

    const int tid  = threadIdx.x;
    const int lane = tid & 31;
    const int w    = tid >> 5;
    const float* Fb = femb + (size_t)b * (NDIM * NDIM);

    // Load F (fp32) -> fp16 swizzled smem. Each thread: 2 chunks of 8 halves.
    {
        const int r  = tid >> 2;
        const int c0 = (tid & 3) * 2;
        #pragma unroll
        for (int cc = 0; cc < 2; cc++) {
            const int c = c0 + cc;
            float4 x0 = *(const float4*)(Fb + r * 64 + c * 8);
            float4 x1 = *(const float4*)(Fb + r * 64 + c * 8 + 4);
            uint4 pk;
            pk.x = h2_as_u32(__floats2half2_rn(x0.x, x0.y));
            pk.y = h2_as_u32(__floats2half2_rn(x0.z, x0.w));
            pk.z = h2_as_u32(__floats2half2_rn(x1.x, x1.y));
            pk.w = h2_as_u32(__floats2half2_rn(x1.z, x1.w));
            *(uint4*)((char*)Fh + swz128(r, c)) = pk;
        }
    }
    // Load kpW (fp32) transposed -> fp16 swizzled smem. 16 scalars per thread.
    #pragma unroll
    for (int k = 0; k < 16; k++) {
        const int idx = tid + k * 256;
        const int d = idx >> 6, e = idx & 63;
        const __half h = __float2half_rn(kpW[idx]);
        const int c = d >> 3;
        *(__half*)((char*)Wt + swz128(e, c) + (d & 7) * 2) = h;
    }
    __syncthreads();

    const int mt = (w & 3) * 16;          // output row tile
    const int nb = (w >> 2) * 32;         // output col base
    const uint32_t a_r    = mt + (lane & 15);
    const uint32_t a_csel = (uint32_t)(lane >> 4);
    const uint32_t b_rb   = nb + ((lane >> 4) << 3) + (lane & 7);
    const uint32_t b_csel = (uint32_t)((lane >> 3) & 1);

    // GEMM1: T = F @ kpW  (A = Fh, B = Wt)
    float acc1[4][4] = {};
    #pragma unroll
    for (int ks = 0; ks < 4; ks++) {
        uint32_t a_f[4];
        ldsm4(a_f, sF + swz128(a_r, ks * 2 + a_csel));
        uint32_t b_f[2][4];
        #pragma unroll
        for (int j = 0; j < 2; j++)
            ldsm4(b_f[j], sW + swz128(b_rb + j * 16, ks * 2 + b_csel));
        #pragma unroll
        for (int ni = 0; ni < 4; ni++)
            mma_fp16(acc1[ni], a_f, b_f[ni >> 1][(ni & 1) * 2],
                     b_f[ni >> 1][(ni & 1) * 2 + 1]);
    }

    // Store T (fp16, swizzled)
    {
        const int tr = mt + (lane >> 2);
        #pragma unroll
        for (int ni = 0; ni < 4; ni++) {
            const int col = nb + ni * 8 + (lane & 3) * 2;
            const int c = col >> 3;
            *(__half2*)((char*)Th + swz128(tr, c) + (col & 7) * 2) =
                __floats2half2_rn(acc1[ni][0], acc1[ni][1]);
            *(__half2*)((char*)Th + swz128(tr + 8, c) + (col & 7) * 2) =
                __floats2half2_rn(acc1[ni][2], acc1[ni][3]);
        }
    }
    __syncthreads();

    // GEMM2: E = T @ F^T  (A = Th, B = Fh; both row-major over K=e)
    float acc2[4][4] = {};
    #pragma unroll
    for (int ks = 0; ks < 4; ks++) {
        uint32_t a_f[4];
        ldsm4(a_f, sT + swz128(a_r, ks * 2 + a_csel));
        uint32_t b_f[2][4];
        #pragma unroll
        for (int j = 0; j < 2; j++)
            ldsm4(b_f[j], sF + swz128(b_rb + j * 16, ks * 2 + b_csel));
        #pragma unroll
        for (int ni = 0; ni < 4; ni++)
            mma_fp16(acc2[ni], a_f, b_f[ni >> 1][(ni & 1) * 2],
                     b_f[ni >> 1][(ni & 1) * 2 + 1]);
    }

    // Scatter E into triu/tril fp16 planes
    __half* tri_row = g_A + (size_t)b * KPAD;            // view 0
    __half* trl_row = g_A + (size_t)(4096 + b) * KPAD;   // view 1
    const int rr = mt + (lane >> 2);
    #pragma unroll
    for (int ni = 0; ni < 4; ni++) {
        const int cb = nb + ni * 8 + (lane & 3) * 2;
        #pragma unroll
        for (int q = 0; q < 4; q++) {
            const int r = rr + (q >> 1) * 8;
            const int c = cb + (q & 1);
            const __half h = __float2half_rn(acc2[ni][q]);
            if (r <= c) tri_row[r * 64 - (r * (r - 1)) / 2 - r + c] = h;
            if (r >= c) trl_row[(r * (r + 1)) / 2 + c] = h;
        }
    }
}

// ---------------------------------------------------------------------------
// Prep kernel: [0, KP_BLOCKS) kp_pair; remainder converts W planes with
// 8 quads per thread (2080 fat CTAs instead of 16640 micro CTAs).
// ---------------------------------------------------------------------------
__global__ __launch_bounds__(256) void prep_kernel(
    const float* __restrict__ femb, const float* __restrict__ kpW,
    const float* __restrict__ Wt, const float* __restrict__ Wl)
{
    const int bid = blockIdx.x;

    if (bid < KP_BLOCKS) {
        kp_pair_body(bid, femb, kpW);
        return;
    }

    // Convert W_triu/W_tril fp32 -> fp16 plane in g_Wc. 8 quads per thread.
    const size_t base = (size_t)(bid - KP_BLOCKS) * 2048 + threadIdx.x;
    #pragma unroll
    for (int i = 0; i < 8; i++) {
        const size_t idx = base + (size_t)i * 256;
        int v = (int)(idx / ((size_t)4096 * 520));
        size_t rem = idx - (size_t)v * 4096 * 520;
        int f = (int)(rem / 520), q = (int)(rem % 520);

        const float* W = v ? Wl : Wt;
        float4 x = reinterpret_cast<const float4*>(W + (size_t)f * KP)[q];

        __half* row = g_Wc + (size_t)(v * 4096 + f) * KPAD;
        __half2* o = reinterpret_cast<__half2*>(row + q * 4);
        o[0] = __floats2half2_rn(x.x, x.y);
        o[1] = __floats2half2_rn(x.z, x.w);
    }
}

// ---------------------------------------------------------------------------
// Kernel B: mma.sync fp16 GEMM (fp32 accumulate), 512 threads = 16 warps.
// EXACT round-10 measured-best configuration:
// CTA tile 128(M) x 256(N), BK=32, warp grid 2M x 8N (warp tile 64x32),
// 5-stage cp.async pipeline (24KB/stage). Appended CTAs do the embs copy.
// ---------------------------------------------------------------------------
#define PL_A 0
#define PL_B 8192           // A plane 8KB, B plane 16KB
#define STAGE_BYTES 24576
#define NSTAGE 5
#define SMEM_GEMM (NSTAGE * STAGE_BYTES)

__global__ void __launch_bounds__(512, 1) view_gemm_kernel(
    float* __restrict__ out, const float* __restrict__ femb)
{
    // ---- appended copy CTAs: segment 0 (embs_flatten) ----
    if (blockIdx.x >= GEMM_BLOCKS) {
        const size_t base = (size_t)(blockIdx.x - GEMM_BLOCKS) * (512 * 8)
                          + threadIdx.x;
        #pragma unroll
        for (int i = 0; i < 8; i++) {
            const size_t q = base + (size_t)i * 512;
            reinterpret_cast<float4*>(out)[q] =
                reinterpret_cast<const float4*>(femb)[q];
        }
        return;
    }

    extern __shared__ char smem[];
    const uint32_t sb0 = smem_to_u32(smem);

    const int tid  = threadIdx.x;
    const int lane = tid & 31;
    const int wid  = tid >> 5;
    const int warpM = wid & 1;        // 0..1  (64 rows each)
    const int warpN = wid >> 1;       // 0..7  (32 cols each)

    const int id   = blockIdx.x;
    const int view = id >> 9;
    const int m0   = ((id >> 4) & 31) * 128;
    const int n0   = (id & 15) * 256;

    const __half* Abase = g_A  + (size_t)(view * 4096 + m0) * KPAD;
    const __half* Bbase = g_Wc + (size_t)(view * 4096 + n0) * KPAD;

    // cp.async: 3 x 16B per thread per stage (1 A chunk + 2 B chunks).
    const int lr = tid >> 2;           // 0..127
    const int lc = tid & 3;            // 16B chunk 0..3
    const __half* srcA  = Abase + (size_t)lr * KPAD + lc * 8;
    const __half* srcB0 = Bbase + (size_t)lr * KPAD + lc * 8;
    const __half* srcB1 = Bbase + (size_t)(lr + 128) * KPAD + lc * 8;
    const uint32_t soA  = PL_A + swz(lr, lc);
    const uint32_t soB0 = PL_B + swz(lr, lc);
    const uint32_t soB1 = PL_B + swz(lr + 128, lc);

    float acc[4][4][4] = {};

    // ---- pipeline prologue: stages 0..3 ----
    #pragma unroll
    for (int s = 0; s < 4; s++) {
        const uint32_t sb = sb0 + s * STAGE_BYTES;
        const size_t kb = (size_t)s * 32;
        cp16(sb + soA,  srcA  + kb);
        cp16(sb + soB0, srcB0 + kb);
        cp16(sb + soB1, srcB1 + kb);
        CP_COMMIT();
    }

    // ldmatrix lane-dependent address components
    const uint32_t a_r = warpM * 64 + (lane & 15);                   // + mi*16
    const uint32_t a_c = (uint32_t)(lane >> 4);                      // + ks*2
    const uint32_t b_r = warpN * 32 + (lane >> 4) * 8 + (lane & 7);  // + j*16
    const uint32_t b_c = (uint32_t)((lane >> 3) & 1);                // + ks*2

    int stage_c = 0;   // compute stage index (mod NSTAGE)
    int stage_l = 4;   // load stage index (mod NSTAGE)

    for (int ch = 0; ch < NCHUNK; ch++) {
        CP_WAIT3();
        __syncthreads();

        // issue loads for ch+4 (overwrites buffer of ch-1, already consumed)
        if (ch + 4 < NCHUNK) {
            const uint32_t sb = sb0 + stage_l * STAGE_BYTES;
            const size_t kb = (size_t)(ch + 4) * 32;
            cp16(sb + soA,  srcA  + kb);
            cp16(sb + soB0, srcB0 + kb);
            cp16(sb + soB1, srcB1 + kb);
        }
        CP_COMMIT();
        if (++stage_l == NSTAGE) stage_l = 0;

        const uint32_t sb = sb0 + stage_c * STAGE_BYTES;
        if (++stage_c == NSTAGE) stage_c = 0;

        #pragma unroll
        for (int ks = 0; ks < 2; ks++) {
            uint32_t b_f[2][4];
            #pragma unroll
            for (int j = 0; j < 2; j++) {
                const uint32_t off = swz(b_r + j * 16, b_c + ks * 2);
                ldsm4(b_f[j], sb + PL_B + off);
            }
            uint32_t a_f[4][4];
            #pragma unroll
            for (int mi = 0; mi < 4; mi++) {
                const uint32_t off = swz(a_r + mi * 16, a_c + ks * 2);
                ldsm4(a_f[mi], sb + PL_A + off);
            }
            #pragma unroll
            for (int mi = 0; mi < 4; mi++) {
                #pragma unroll
                for (int ni = 0; ni < 4; ni++) {
                    const int j = ni >> 1, h = (ni & 1) * 2;
                    mma_fp16(acc[mi][ni], a_f[mi], b_f[j][h], b_f[j][h + 1]);
                }
            }
        }
    }

    // ---- epilogue: direct float2 stores ----
    float* C = out + (size_t)(1 + view) * EMB_ELEMS;
    const int rbase = m0 + warpM * 64 + (lane >> 2);
    const int cbase = n0 + warpN * 32 + (lane & 3) * 2;
    #pragma unroll
    for (int mi = 0; mi < 4; mi++) {
        #pragma unroll
        for (int ni = 0; ni < 4; ni++) {
            const size_t r0 = (size_t)(rbase + mi * 16);
            const int cc = cbase + ni * 8;
            *reinterpret_cast<float2*>(&C[r0 * FDIM + cc]) =
                make_float2(acc[mi][ni][0], acc[mi][ni][1]);
            *reinterpret_cast<float2*>(&C[(r0 + 8) * FDIM + cc]) =
                make_float2(acc[mi][ni][2], acc[mi][ni][3]);
        }
    }
}

// ---------------------------------------------------------------------------
// Host launch
// Inputs: feature_emb, kp_W, W_triu, W_tril (all fp32)
// Output: [embs_flatten | view_1 | view_2], each 4096*4096 fp32.
// ---------------------------------------------------------------------------
extern "C" void kernel_launch(void* const* d_in, const int* in_sizes, int n_in,
                              void* d_out, int out_size)
{
    const float* femb   = (const float*)d_in[0];
    const float* kpW    = (const float*)d_in[1];
    const float* W_triu = (const float*)d_in[2];
    const float* W_tril = (const float*)d_in[3];
    float* out = (float*)d_out;

    // Prep: kp_pair (1 batch/block) + W conversion (fat CTAs), one launch
    prep_kernel<<<PREP_BLOCKS, 256>>>(femb, kpW, W_triu, W_tril);

    // GEMMs + embs_flatten copy in one grid
    cudaFuncSetAttribute(view_gemm_kernel,
                         cudaFuncAttributeMaxDynamicSharedMemorySize, SMEM_GEMM);
    view_gemm_kernel<<<GEMM_BLOCKS + COPYG_BLOCKS, 512, SMEM_GEMM>>>(out, femb);
}

// round 16
// speedup vs baseline: 1.0951x; 1.0008x over previous
#include <cuda_runtime.h>
#include <cuda_fp16.h>
#include <cstdint>

// ---------------------------------------------------------------------------
// Problem constants
// ---------------------------------------------------------------------------
#define BATCH 4096
#define NDIM  64
#define FDIM  4096
#define KP    2080          // N*(N+1)/2
#define KPAD  2112          // KP padded (66 chunks of 32)
#define EMB_ELEMS (4096u*4096u)
#define NCHUNK (KPAD/32)    // 66

// Prep kernel partition (kp_pair + W conversion; copy lives in the GEMM grid)
#define KP_BLOCKS    4096                       // 1 batch per block (round-10)
#define CONV_BLOCKS  2080                       // 2*4096*520 quads / (256*8)
#define PREP_BLOCKS  (KP_BLOCKS + CONV_BLOCKS)

// GEMM grid: 1024 gemm CTAs + 1024 copy CTAs
#define GEMM_BLOCKS  1024
#define COPYG_BLOCKS 1024                       // 4M float4 / (512 thr * 8)

// fp16 operand planes. Rows [0,4096) = view0 (triu / W_triu), [4096,8192) = view1.
// Pad cols [2080,2112) stay zero (.bss zero-init, never written).
__device__ __align__(1024) __half g_A [(size_t)8192 * KPAD];
__device__ __align__(1024) __half g_Wc[(size_t)8192 * KPAD];

// ---------------------------------------------------------------------------
// Small helpers
// ---------------------------------------------------------------------------
__device__ __forceinline__ uint32_t smem_to_u32(const void* p) {
    uint32_t a;
    asm("{ .reg .u64 t; cvta.to.shared.u64 t, %1; cvt.u32.u64 %0, t; }"
        : "=r"(a) : "l"(p));
    return a;
}

__device__ __forceinline__ uint32_t h2_as_u32(__half2 h) {
    uint32_t u;
    __builtin_memcpy(&u, &h, 4);
    return u;
}

__device__ __forceinline__ void cp16(uint32_t dst, const void* src) {
    asm volatile("cp.async.cg.shared.global [%0], [%1], 16;"
                 :: "r"(dst), "l"(src));
}
#define CP_COMMIT() asm volatile("cp.async.commit_group;" ::: "memory")
#define CP_WAIT3()  asm volatile("cp.async.wait_group 3;" ::: "memory")

__device__ __forceinline__ void ldsm4(uint32_t (&r)[4], uint32_t addr) {
    asm volatile("ldmatrix.sync.aligned.m8n8.x4.shared.b16 {%0,%1,%2,%3}, [%4];"
                 : "=r"(r[0]), "=r"(r[1]), "=r"(r[2]), "=r"(r[3]) : "r"(addr));
}

__device__ __forceinline__ void mma_fp16(float (&d)[4], const uint32_t (&a)[4],
                                         uint32_t b0, uint32_t b1) {
    asm volatile(
        "mma.sync.aligned.m16n8k16.row.col.f32.f16.f16.f32 "
        "{%0,%1,%2,%3}, {%4,%5,%6,%7}, {%8,%9}, {%0,%1,%2,%3};"
        : "+f"(d[0]), "+f"(d[1]), "+f"(d[2]), "+f"(d[3])
        : "r"(a[0]), "r"(a[1]), "r"(a[2]), "r"(a[3]), "r"(b0), "r"(b1));
}

// XOR swizzle for 64B rows (GEMM stage planes): row r, 16B-chunk c (0..3).
__device__ __forceinline__ uint32_t swz(uint32_t r, uint32_t c) {
    return (r * 4u + (c ^ ((r >> 1) & 3u))) * 16u;
}

// Full SW128 XOR swizzle for 128B rows (kp_pair tiles): row r, chunk c (0..7).
__device__ __forceinline__ uint32_t swz128(uint32_t r, uint32_t c) {
    return r * 128u + ((c ^ (r & 7u)) << 4);
}

// ---------------------------------------------------------------------------
// kp_pair body (round-10 exact): per-batch embs_kp = F @ kpW @ F^T via
// mma.sync, scatter triu/tril as fp16 into g_A. 256 threads = 8 warps.
// ---------------------------------------------------------------------------
__device__ void kp_pair_body(int b, const float* __restrict__ femb,
                             const float* __restrict__ kpW)
{
    __shared__ __align__(128) __half Fh[64 * 64];  // F,  swizzled 128B rows
    __shared__ __align__(128) __half Wt[64 * 64];  // kpW^T, swizzled
    __shared__ __align__(128) __half Th[64 * 64];  // T = F@kpW, swizzled

    const uint32_t sF = smem_to_u32(Fh);
    const uint32_t sW = smem_to_u32(Wt);
    const uint32_t sT = smem_to_u32(Th);

    const int tid  = threadIdx.x;
    const int lane = tid & 31;
    const int w    = tid >> 5;
    const float* Fb = femb + (size_t)b * (NDIM * NDIM);

    // Load F (fp32) -> fp16 swizzled smem. Each thread: 2 chunks of 8 halves.
    {
        const int r  = tid >> 2;
        const int c0 = (tid & 3) * 2;
        #pragma unroll
        for (int cc = 0; cc < 2; cc++) {
            const int c = c0 + cc;
            float4 x0 = *(const float4*)(Fb + r * 64 + c * 8);
            float4 x1 = *(const float4*)(Fb + r * 64 + c * 8 + 4);
            uint4 pk;
            pk.x = h2_as_u32(__floats2half2_rn(x0.x, x0.y));
            pk.y = h2_as_u32(__floats2half2_rn(x0.z, x0.w));
            pk.z = h2_as_u32(__floats2half2_rn(x1.x, x1.y));
            pk.w = h2_as_u32(__floats2half2_rn(x1.z, x1.w));
            *(uint4*)((char*)Fh + swz128(r, c)) = pk;
        }
    }
    // Load kpW (fp32) transposed -> fp16 swizzled smem. 16 scalars per thread.
    #pragma unroll
    for (int k = 0; k < 16; k++) {
        const int idx = tid + k * 256;
        const int d = idx >> 6, e = idx & 63;
        const __half h = __float2half_rn(kpW[idx]);
        const int c = d >> 3;
        *(__half*)((char*)Wt + swz128(e, c) + (d & 7) * 2) = h;
    }
    __syncthreads();

    const int mt = (w & 3) * 16;          // output row tile
    const int nb = (w >> 2) * 32;         // output col base
    const uint32_t a_r    = mt + (lane & 15);
    const uint32_t a_csel = (uint32_t)(lane >> 4);
    const uint32_t b_rb   = nb + ((lane >> 4) << 3) + (lane & 7);
    const uint32_t b_csel = (uint32_t)((lane >> 3) & 1);

    // GEMM1: T = F @ kpW  (A = Fh, B = Wt)
    float acc1[4][4] = {};
    #pragma unroll
    for (int ks = 0; ks < 4; ks++) {
        uint32_t a_f[4];
        ldsm4(a_f, sF + swz128(a_r, ks * 2 + a_csel));
        uint32_t b_f[2][4];
        #pragma unroll
        for (int j = 0; j < 2; j++)
            ldsm4(b_f[j], sW + swz128(b_rb + j * 16, ks * 2 + b_csel));
        #pragma unroll
        for (int ni = 0; ni < 4; ni++)
            mma_fp16(acc1[ni], a_f, b_f[ni >> 1][(ni & 1) * 2],
                     b_f[ni >> 1][(ni & 1) * 2 + 1]);
    }

    // Store T (fp16, swizzled)
    {
        const int tr = mt + (lane >> 2);
        #pragma unroll
        for (int ni = 0; ni < 4; ni++) {
            const int col = nb + ni * 8 + (lane & 3) * 2;
            const int c = col >> 3;
            *(__half2*)((char*)Th + swz128(tr, c) + (col & 7) * 2) =
                __floats2half2_rn(acc1[ni][0], acc1[ni][1]);
            *(__half2*)((char*)Th + swz128(tr + 8, c) + (col & 7) * 2) =
                __floats2half2_rn(acc1[ni][2], acc1[ni][3]);
        }
    }
    __syncthreads();

    // GEMM2: E = T @ F^T  (A = Th, B = Fh; both row-major over K=e)
    float acc2[4][4] = {};
    #pragma unroll
    for (int ks = 0; ks < 4; ks++) {
        uint32_t a_f[4];
        ldsm4(a_f, sT + swz128(a_r, ks * 2 + a_csel));
        uint32_t b_f[2][4];
        #pragma unroll
        for (int j = 0; j < 2; j++)
            ldsm4(b_f[j], sF + swz128(b_rb + j * 16, ks * 2 + b_csel));
        #pragma unroll
        for (int ni = 0; ni < 4; ni++)
            mma_fp16(acc2[ni], a_f, b_f[ni >> 1][(ni & 1) * 2],
                     b_f[ni >> 1][(ni & 1) * 2 + 1]);
    }

    // Scatter E into triu/tril fp16 planes
    __half* tri_row = g_A + (size_t)b * KPAD;            // view 0
    __half* trl_row = g_A + (size_t)(4096 + b) * KPAD;   // view 1
    const int rr = mt + (lane >> 2);
    #pragma unroll
    for (int ni = 0; ni < 4; ni++) {
        const int cb = nb + ni * 8 + (lane & 3) * 2;
        #pragma unroll
        for (int q = 0; q < 4; q++) {
            const int r = rr + (q >> 1) * 8;
            const int c = cb + (q & 1);
            const __half h = __float2half_rn(acc2[ni][q]);
            if (r <= c) tri_row[r * 64 - (r * (r - 1)) / 2 - r + c] = h;
            if (r >= c) trl_row[(r * (r + 1)) / 2 + c] = h;
        }
    }
}

// ---------------------------------------------------------------------------
// Prep kernel: [0, KP_BLOCKS) kp_pair; remainder converts W planes with
// 8 quads per thread. Each CTA triggers programmatic completion after its
// stores so the PDL-launched GEMM can overlap prep's tail.
// ---------------------------------------------------------------------------
__global__ __launch_bounds__(256) void prep_kernel(
    const float* __restrict__ femb, const float* __restrict__ kpW,
    const float* __restrict__ Wt, const float* __restrict__ Wl)
{
    const int bid = blockIdx.x;

    if (bid < KP_BLOCKS) {
        kp_pair_body(bid, femb, kpW);
        cudaTriggerProgrammaticLaunchCompletion();
        return;
    }

    // Convert W_triu/W_tril fp32 -> fp16 plane in g_Wc. 8 quads per thread.
    const size_t base = (size_t)(bid - KP_BLOCKS) * 2048 + threadIdx.x;
    #pragma unroll
    for (int i = 0; i < 8; i++) {
        const size_t idx = base + (size_t)i * 256;
        int v = (int)(idx / ((size_t)4096 * 520));
        size_t rem = idx - (size_t)v * 4096 * 520;
        int f = (int)(rem / 520), q = (int)(rem % 520);

        const float* W = v ? Wl : Wt;
        float4 x = reinterpret_cast<const float4*>(W + (size_t)f * KP)[q];

        __half* row = g_Wc + (size_t)(v * 4096 + f) * KPAD;
        __half2* o = reinterpret_cast<__half2*>(row + q * 4);
        o[0] = __floats2half2_rn(x.x, x.y);
        o[1] = __floats2half2_rn(x.z, x.w);
    }
    cudaTriggerProgrammaticLaunchCompletion();
}

// ---------------------------------------------------------------------------
// Kernel B: mma.sync fp16 GEMM (fp32 accumulate), 512 threads = 16 warps.
// EXACT round-10 measured-best configuration. Launched with PDL: GEMM CTAs
// grid-dependency-sync before touching g_A/g_Wc; copy CTAs (prep-independent)
// skip the sync and overlap with prep.
// ---------------------------------------------------------------------------
#define PL_A 0
#define PL_B 8192           // A plane 8KB, B plane 16KB
#define STAGE_BYTES 24576
#define NSTAGE 5
#define SMEM_GEMM (NSTAGE * STAGE_BYTES)

__global__ void __launch_bounds__(512, 1) view_gemm_kernel(
    float* __restrict__ out, const float* __restrict__ femb)
{
    // ---- appended copy CTAs: segment 0 (embs_flatten); no prep dependency ----
    if (blockIdx.x >= GEMM_BLOCKS) {
        const size_t base = (size_t)(blockIdx.x - GEMM_BLOCKS) * (512 * 8)
                          + threadIdx.x;
        #pragma unroll
        for (int i = 0; i < 8; i++) {
            const size_t q = base + (size_t)i * 512;
            reinterpret_cast<float4*>(out)[q] =
                reinterpret_cast<const float4*>(femb)[q];
        }
        return;
    }

    extern __shared__ char smem[];
    const uint32_t sb0 = smem_to_u32(smem);

    const int tid  = threadIdx.x;
    const int lane = tid & 31;
    const int wid  = tid >> 5;
    const int warpM = wid & 1;        // 0..1  (64 rows each)
    const int warpN = wid >> 1;       // 0..7  (32 cols each)

    const int id   = blockIdx.x;
    const int view = id >> 9;
    const int m0   = ((id >> 4) & 31) * 128;
    const int n0   = (id & 15) * 256;

    const __half* Abase = g_A  + (size_t)(view * 4096 + m0) * KPAD;
    const __half* Bbase = g_Wc + (size_t)(view * 4096 + n0) * KPAD;

    // cp.async: 3 x 16B per thread per stage (1 A chunk + 2 B chunks).
    const int lr = tid >> 2;           // 0..127
    const int lc = tid & 3;            // 16B chunk 0..3
    const __half* srcA  = Abase + (size_t)lr * KPAD + lc * 8;
    const __half* srcB0 = Bbase + (size_t)lr * KPAD + lc * 8;
    const __half* srcB1 = Bbase + (size_t)(lr + 128) * KPAD + lc * 8;
    const uint32_t soA  = PL_A + swz(lr, lc);
    const uint32_t soB0 = PL_B + swz(lr, lc);
    const uint32_t soB1 = PL_B + swz(lr + 128, lc);

    float acc[4][4][4] = {};

    // Wait for prep's g_A / g_Wc stores to be visible (PDL dependency).
    cudaGridDependencySynchronize();

    // ---- pipeline prologue: stages 0..3 ----
    #pragma unroll
    for (int s = 0; s < 4; s++) {
        const uint32_t sb = sb0 + s * STAGE_BYTES;
        const size_t kb = (size_t)s * 32;
        cp16(sb + soA,  srcA  + kb);
        cp16(sb + soB0, srcB0 + kb);
        cp16(sb + soB1, srcB1 + kb);
        CP_COMMIT();
    }

    // ldmatrix lane-dependent address components
    const uint32_t a_r = warpM * 64 + (lane & 15);                   // + mi*16
    const uint32_t a_c = (uint32_t)(lane >> 4);                      // + ks*2
    const uint32_t b_r = warpN * 32 + (lane >> 4) * 8 + (lane & 7);  // + j*16
    const uint32_t b_c = (uint32_t)((lane >> 3) & 1);                // + ks*2

    int stage_c = 0;   // compute stage index (mod NSTAGE)
    int stage_l = 4;   // load stage index (mod NSTAGE)

    for (int ch = 0; ch < NCHUNK; ch++) {
        CP_WAIT3();
        __syncthreads();

        // issue loads for ch+4 (overwrites buffer of ch-1, already consumed)
        if (ch + 4 < NCHUNK) {
            const uint32_t sb = sb0 + stage_l * STAGE_BYTES;
            const size_t kb = (size_t)(ch + 4) * 32;
            cp16(sb + soA,  srcA  + kb);
            cp16(sb + soB0, srcB0 + kb);
            cp16(sb + soB1, srcB1 + kb);
        }
        CP_COMMIT();
        if (++stage_l == NSTAGE) stage_l = 0;

        const uint32_t sb = sb0 + stage_c * STAGE_BYTES;
        if (++stage_c == NSTAGE) stage_c = 0;

        #pragma unroll
        for (int ks = 0; ks < 2; ks++) {
            uint32_t b_f[2][4];
            #pragma unroll
            for (int j = 0; j < 2; j++) {
                const uint32_t off = swz(b_r + j * 16, b_c + ks * 2);
                ldsm4(b_f[j], sb + PL_B + off);
            }
            uint32_t a_f[4][4];
            #pragma unroll
            for (int mi = 0; mi < 4; mi++) {
                const uint32_t off = swz(a_r + mi * 16, a_c + ks * 2);
                ldsm4(a_f[mi], sb + PL_A + off);
            }
            #pragma unroll
            for (int mi = 0; mi < 4; mi++) {
                #pragma unroll
                for (int ni = 0; ni < 4; ni++) {
                    const int j = ni >> 1, h = (ni & 1) * 2;
                    mma_fp16(acc[mi][ni], a_f[mi], b_f[j][h], b_f[j][h + 1]);
                }
            }
        }
    }

    // ---- epilogue: direct float2 stores ----
    float* C = out + (size_t)(1 + view) * EMB_ELEMS;
    const int rbase = m0 + warpM * 64 + (lane >> 2);
    const int cbase = n0 + warpN * 32 + (lane & 3) * 2;
    #pragma unroll
    for (int mi = 0; mi < 4; mi++) {
        #pragma unroll
        for (int ni = 0; ni < 4; ni++) {
            const size_t r0 = (size_t)(rbase + mi * 16);
            const int cc = cbase + ni * 8;
            *reinterpret_cast<float2*>(&C[r0 * FDIM + cc]) =
                make_float2(acc[mi][ni][0], acc[mi][ni][1]);
            *reinterpret_cast<float2*>(&C[(r0 + 8) * FDIM + cc]) =
                make_float2(acc[mi][ni][2], acc[mi][ni][3]);
        }
    }
}

// ---------------------------------------------------------------------------
// Host launch
// Inputs: feature_emb, kp_W, W_triu, W_tril (all fp32)
// Output: [embs_flatten | view_1 | view_2], each 4096*4096 fp32.
// ---------------------------------------------------------------------------
extern "C" void kernel_launch(void* const* d_in, const int* in_sizes, int n_in,
                              void* d_out, int out_size)
{
    const float* femb   = (const float*)d_in[0];
    const float* kpW    = (const float*)d_in[1];
    const float* W_triu = (const float*)d_in[2];
    const float* W_tril = (const float*)d_in[3];
    float* out = (float*)d_out;

    // Prep: kp_pair + W conversion (one launch)
    prep_kernel<<<PREP_BLOCKS, 256>>>(femb, kpW, W_triu, W_tril);

    // GEMMs + embs_flatten copy, PDL-launched to overlap prep's tail
    cudaFuncSetAttribute(view_gemm_kernel,
                         cudaFuncAttributeMaxDynamicSharedMemorySize, SMEM_GEMM);

    cudaLaunchConfig_t cfg = {};
    cfg.gridDim  = dim3(GEMM_BLOCKS + COPYG_BLOCKS, 1, 1);
    cfg.blockDim = dim3(512, 1, 1);
    cfg.dynamicSmemBytes = SMEM_GEMM;
    cfg.stream = 0;
    cudaLaunchAttribute attrs[1];
    attrs[0].id = cudaLaunchAttributeProgrammaticStreamSerialization;
    attrs[0].val.programmaticStreamSerializationAllowed = 1;
    cfg.attrs = attrs;
    cfg.numAttrs = 1;
    cudaLaunchKernelEx(&cfg, view_gemm_kernel, out, (const float*)femb);
}

// round 17
// speedup vs baseline: 1.1644x; 1.0633x over previous
#include <cuda_runtime.h>
#include <cuda_fp16.h>
#include <cstdint>

// ---------------------------------------------------------------------------
// Problem constants
// ---------------------------------------------------------------------------
#define BATCH 4096
#define NDIM  64
#define FDIM  4096
#define KP    2080          // N*(N+1)/2
#define KPAD  2112          // KP padded (66 chunks of 32)
#define EMB_ELEMS (4096u*4096u)
#define NCHUNK (KPAD/32)    // 66

// Prep kernel partition
#define KP_BLOCKS    4096
#define CONV_BLOCKS  2080                       // 2*4096*520 quads / (256*8)
#define PREP_BLOCKS  (KP_BLOCKS + CONV_BLOCKS)

// GEMM grid: 2048 gemm CTAs (2 views x 32 x 32 tiles of 128x128) + copy CTAs
#define GEMM_BLOCKS  2048
#define COPYG_BLOCKS 2048                       // 4M float4 / (256 thr * 8)

// fp16 operand planes. Rows [0,4096) = view0 (triu / W_triu), [4096,8192) = view1.
// Pad cols [2080,2112) stay zero (.bss zero-init, never written).
__device__ __align__(1024) __half g_A [(size_t)8192 * KPAD];
__device__ __align__(1024) __half g_Wc[(size_t)8192 * KPAD];

// ---------------------------------------------------------------------------
// Small helpers
// ---------------------------------------------------------------------------
__device__ __forceinline__ uint32_t smem_to_u32(const void* p) {
    uint32_t a;
    asm("{ .reg .u64 t; cvta.to.shared.u64 t, %1; cvt.u32.u64 %0, t; }"
        : "=r"(a) : "l"(p));
    return a;
}

__device__ __forceinline__ uint32_t h2_as_u32(__half2 h) {
    uint32_t u;
    __builtin_memcpy(&u, &h, 4);
    return u;
}

__device__ __forceinline__ void cp16(uint32_t dst, const void* src) {
    asm volatile("cp.async.cg.shared.global [%0], [%1], 16;"
                 :: "r"(dst), "l"(src));
}
#define CP_COMMIT() asm volatile("cp.async.commit_group;" ::: "memory")
#define CP_WAIT3()  asm volatile("cp.async.wait_group 3;" ::: "memory")

__device__ __forceinline__ void ldsm4(uint32_t (&r)[4], uint32_t addr) {
    asm volatile("ldmatrix.sync.aligned.m8n8.x4.shared.b16 {%0,%1,%2,%3}, [%4];"
                 : "=r"(r[0]), "=r"(r[1]), "=r"(r[2]), "=r"(r[3]) : "r"(addr));
}

__device__ __forceinline__ void mma_fp16(float (&d)[4], const uint32_t (&a)[4],
                                         uint32_t b0, uint32_t b1) {
    asm volatile(
        "mma.sync.aligned.m16n8k16.row.col.f32.f16.f16.f32 "
        "{%0,%1,%2,%3}, {%4,%5,%6,%7}, {%8,%9}, {%0,%1,%2,%3};"
        : "+f"(d[0]), "+f"(d[1]), "+f"(d[2]), "+f"(d[3])
        : "r"(a[0]), "r"(a[1]), "r"(a[2]), "r"(a[3]), "r"(b0), "r"(b1));
}

// XOR swizzle for 64B rows (GEMM stage planes): row r, 16B-chunk c (0..3).
__device__ __forceinline__ uint32_t swz(uint32_t r, uint32_t c) {
    return (r * 4u + (c ^ ((r >> 1) & 3u))) * 16u;
}

// Full SW128 XOR swizzle for 128B rows (kp_pair tiles): row r, chunk c (0..7).
__device__ __forceinline__ uint32_t swz128(uint32_t r, uint32_t c) {
    return r * 128u + ((c ^ (r & 7u)) << 4);
}

// ---------------------------------------------------------------------------
// kp_pair body (round-10 exact): per-batch embs_kp = F @ kpW @ F^T via
// mma.sync, scatter triu/tril as fp16 into g_A. 256 threads = 8 warps.
// ---------------------------------------------------------------------------
__device__ void kp_pair_body(int b, const float* __restrict__ femb,
                             const float* __restrict__ kpW)
{
    __shared__ __align__(128) __half Fh[64 * 64];
    __shared__ __align__(128) __half Wt[64 * 64];
    __shared__ __align__(128) __half Th[64 * 64];

    const uint32_t sF = smem_to_u32(Fh);
    const uint32_t sW = smem_to_u32(Wt);
    const uint32_t sT = smem_to_u32(Th);

    const int tid  = threadIdx.x;
    const int lane = tid & 31;
    const int w    = tid >> 5;
    const float* Fb = femb + (size_t)b * (NDIM * NDIM);

    {
        const int r  = tid >> 2;
        const int c0 = (tid & 3) * 2;
        #pragma unroll
        for (int cc = 0; cc < 2; cc++) {
            const int c = c0 + cc;
            float4 x0 = *(const float4*)(Fb + r * 64 + c * 8);
            float4 x1 = *(const float4*)(Fb + r * 64 + c * 8 + 4);
            uint4 pk;
            pk.x = h2_as_u32(__floats2half2_rn(x0.x, x0.y));
            pk.y = h2_as_u32(__floats2half2_rn(x0.z, x0.w));
            pk.z = h2_as_u32(__floats2half2_rn(x1.x, x1.y));
            pk.w = h2_as_u32(__floats2half2_rn(x1.z, x1.w));
            *(uint4*)((char*)Fh + swz128(r, c)) = pk;
        }
    }
    #pragma unroll
    for (int k = 0; k < 16; k++) {
        const int idx = tid + k * 256;
        const int d = idx >> 6, e = idx & 63;
        const __half h = __float2half_rn(kpW[idx]);
        const int c = d >> 3;
        *(__half*)((char*)Wt + swz128(e, c) + (d & 7) * 2) = h;
    }
    __syncthreads();

    const int mt = (w & 3) * 16;
    const int nb = (w >> 2) * 32;
    const uint32_t a_r    = mt + (lane & 15);
    const uint32_t a_csel = (uint32_t)(lane >> 4);
    const uint32_t b_rb   = nb + ((lane >> 4) << 3) + (lane & 7);
    const uint32_t b_csel = (uint32_t)((lane >> 3) & 1);

    float acc1[4][4] = {};
    #pragma unroll
    for (int ks = 0; ks < 4; ks++) {
        uint32_t a_f[4];
        ldsm4(a_f, sF + swz128(a_r, ks * 2 + a_csel));
        uint32_t b_f[2][4];
        #pragma unroll
        for (int j = 0; j < 2; j++)
            ldsm4(b_f[j], sW + swz128(b_rb + j * 16, ks * 2 + b_csel));
        #pragma unroll
        for (int ni = 0; ni < 4; ni++)
            mma_fp16(acc1[ni], a_f, b_f[ni >> 1][(ni & 1) * 2],
                     b_f[ni >> 1][(ni & 1) * 2 + 1]);
    }

    {
        const int tr = mt + (lane >> 2);
        #pragma unroll
        for (int ni = 0; ni < 4; ni++) {
            const int col = nb + ni * 8 + (lane & 3) * 2;
            const int c = col >> 3;
            *(__half2*)((char*)Th + swz128(tr, c) + (col & 7) * 2) =
                __floats2half2_rn(acc1[ni][0], acc1[ni][1]);
            *(__half2*)((char*)Th + swz128(tr + 8, c) + (col & 7) * 2) =
                __floats2half2_rn(acc1[ni][2], acc1[ni][3]);
        }
    }
    __syncthreads();

    float acc2[4][4] = {};
    #pragma unroll
    for (int ks = 0; ks < 4; ks++) {
        uint32_t a_f[4];
        ldsm4(a_f, sT + swz128(a_r, ks * 2 + a_csel));
        uint32_t b_f[2][4];
        #pragma unroll
        for (int j = 0; j < 2; j++)
            ldsm4(b_f[j], sF + swz128(b_rb + j * 16, ks * 2 + b_csel));
        #pragma unroll
        for (int ni = 0; ni < 4; ni++)
            mma_fp16(acc2[ni], a_f, b_f[ni >> 1][(ni & 1) * 2],
                     b_f[ni >> 1][(ni & 1) * 2 + 1]);
    }

    __half* tri_row = g_A + (size_t)b * KPAD;
    __half* trl_row = g_A + (size_t)(4096 + b) * KPAD;
    const int rr = mt + (lane >> 2);
    #pragma unroll
    for (int ni = 0; ni < 4; ni++) {
        const int cb = nb + ni * 8 + (lane & 3) * 2;
        #pragma unroll
        for (int q = 0; q < 4; q++) {
            const int r = rr + (q >> 1) * 8;
            const int c = cb + (q & 1);
            const __half h = __float2half_rn(acc2[ni][q]);
            if (r <= c) tri_row[r * 64 - (r * (r - 1)) / 2 - r + c] = h;
            if (r >= c) trl_row[(r * (r + 1)) / 2 + c] = h;
        }
    }
}

// ---------------------------------------------------------------------------
// Prep kernel: [0, KP_BLOCKS) kp_pair; remainder converts W planes.
// ---------------------------------------------------------------------------
__global__ __launch_bounds__(256) void prep_kernel(
    const float* __restrict__ femb, const float* __restrict__ kpW,
    const float* __restrict__ Wt, const float* __restrict__ Wl)
{
    const int bid = blockIdx.x;

    if (bid < KP_BLOCKS) {
        kp_pair_body(bid, femb, kpW);
        cudaTriggerProgrammaticLaunchCompletion();
        return;
    }

    const size_t base = (size_t)(bid - KP_BLOCKS) * 2048 + threadIdx.x;
    #pragma unroll
    for (int i = 0; i < 8; i++) {
        const size_t idx = base + (size_t)i * 256;
        int v = (int)(idx / ((size_t)4096 * 520));
        size_t rem = idx - (size_t)v * 4096 * 520;
        int f = (int)(rem / 520), q = (int)(rem % 520);

        const float* W = v ? Wl : Wt;
        float4 x = reinterpret_cast<const float4*>(W + (size_t)f * KP)[q];

        __half* row = g_Wc + (size_t)(v * 4096 + f) * KPAD;
        __half2* o = reinterpret_cast<__half2*>(row + q * 4);
        o[0] = __floats2half2_rn(x.x, x.y);
        o[1] = __floats2half2_rn(x.z, x.w);
    }
    cudaTriggerProgrammaticLaunchCompletion();
}

// ---------------------------------------------------------------------------
// Kernel B: mma.sync fp16 GEMM (fp32 accumulate), 256 threads = 8 warps,
// CTA tile 128(M) x 128(N), warp grid 2M x 4N (warp tile 64x32 — round-10
// inner loop verbatim), BK=32, 5-stage cp.async pipeline (16KB/stage).
// TWO CTAs co-resident per SM (80KB smem + 32K regs each): when one CTA's
// warps stall at a barrier/wait, the other's feed the tensor pipe.
// Appended CTAs do the embs_flatten copy.
// ---------------------------------------------------------------------------
#define PL_A 0
#define PL_B 8192           // A plane 8KB (128 rows x 64B), B plane 8KB
#define STAGE_BYTES 16384
#define NSTAGE 5
#define SMEM_GEMM (NSTAGE * STAGE_BYTES)

__global__ void __launch_bounds__(256, 2) view_gemm_kernel(
    float* __restrict__ out, const float* __restrict__ femb)
{
    // ---- appended copy CTAs: segment 0 (embs_flatten); no prep dependency ----
    if (blockIdx.x >= GEMM_BLOCKS) {
        const size_t base = (size_t)(blockIdx.x - GEMM_BLOCKS) * (256 * 8)
                          + threadIdx.x;
        #pragma unroll
        for (int i = 0; i < 8; i++) {
            const size_t q = base + (size_t)i * 256;
            reinterpret_cast<float4*>(out)[q] =
                reinterpret_cast<const float4*>(femb)[q];
        }
        return;
    }

    extern __shared__ char smem[];
    const uint32_t sb0 = smem_to_u32(smem);

    const int tid  = threadIdx.x;
    const int lane = tid & 31;
    const int wid  = tid >> 5;
    const int warpM = wid & 1;        // 0..1  (64 rows each)
    const int warpN = wid >> 1;       // 0..3  (32 cols each)

    const int id   = blockIdx.x;
    const int view = id >> 10;                 // 1024 tiles per view
    const int m0   = ((id >> 5) & 31) * 128;
    const int n0   = (id & 31) * 128;

    const __half* Abase = g_A  + (size_t)(view * 4096 + m0) * KPAD;
    const __half* Bbase = g_Wc + (size_t)(view * 4096 + n0) * KPAD;

    // cp.async: 4 x 16B per thread per stage (2 A rows + 2 B rows).
    const int lr = tid >> 2;           // 0..63
    const int lc = tid & 3;            // 16B chunk 0..3
    const __half* srcA0 = Abase + (size_t)lr * KPAD + lc * 8;
    const __half* srcA1 = Abase + (size_t)(lr + 64) * KPAD + lc * 8;
    const __half* srcB0 = Bbase + (size_t)lr * KPAD + lc * 8;
    const __half* srcB1 = Bbase + (size_t)(lr + 64) * KPAD + lc * 8;
    const uint32_t soA0 = PL_A + swz(lr, lc);
    const uint32_t soA1 = PL_A + swz(lr + 64, lc);
    const uint32_t soB0 = PL_B + swz(lr, lc);
    const uint32_t soB1 = PL_B + swz(lr + 64, lc);

    float acc[4][4][4] = {};

    // Wait for prep's g_A / g_Wc stores to be visible (PDL dependency).
    cudaGridDependencySynchronize();

    // ---- pipeline prologue: stages 0..3 ----
    #pragma unroll
    for (int s = 0; s < 4; s++) {
        const uint32_t sb = sb0 + s * STAGE_BYTES;
        const size_t kb = (size_t)s * 32;
        cp16(sb + soA0, srcA0 + kb);
        cp16(sb + soA1, srcA1 + kb);
        cp16(sb + soB0, srcB0 + kb);
        cp16(sb + soB1, srcB1 + kb);
        CP_COMMIT();
    }

    // ldmatrix lane-dependent address components
    const uint32_t a_r = warpM * 64 + (lane & 15);                   // + mi*16
    const uint32_t a_c = (uint32_t)(lane >> 4);                      // + ks*2
    const uint32_t b_r = warpN * 32 + (lane >> 4) * 8 + (lane & 7);  // + j*16
    const uint32_t b_c = (uint32_t)((lane >> 3) & 1);                // + ks*2

    int stage_c = 0;   // compute stage index (mod NSTAGE)
    int stage_l = 4;   // load stage index (mod NSTAGE)

    for (int ch = 0; ch < NCHUNK; ch++) {
        CP_WAIT3();
        __syncthreads();

        // issue loads for ch+4 (overwrites buffer of ch-1, already consumed)
        if (ch + 4 < NCHUNK) {
            const uint32_t sb = sb0 + stage_l * STAGE_BYTES;
            const size_t kb = (size_t)(ch + 4) * 32;
            cp16(sb + soA0, srcA0 + kb);
            cp16(sb + soA1, srcA1 + kb);
            cp16(sb + soB0, srcB0 + kb);
            cp16(sb + soB1, srcB1 + kb);
        }
        CP_COMMIT();
        if (++stage_l == NSTAGE) stage_l = 0;

        const uint32_t sb = sb0 + stage_c * STAGE_BYTES;
        if (++stage_c == NSTAGE) stage_c = 0;

        #pragma unroll
        for (int ks = 0; ks < 2; ks++) {
            uint32_t b_f[2][4];
            #pragma unroll
            for (int j = 0; j < 2; j++) {
                const uint32_t off = swz(b_r + j * 16, b_c + ks * 2);
                ldsm4(b_f[j], sb + PL_B + off);
            }
            uint32_t a_f[4][4];
            #pragma unroll
            for (int mi = 0; mi < 4; mi++) {
                const uint32_t off = swz(a_r + mi * 16, a_c + ks * 2);
                ldsm4(a_f[mi], sb + PL_A + off);
            }
            #pragma unroll
            for (int mi = 0; mi < 4; mi++) {
                #pragma unroll
                for (int ni = 0; ni < 4; ni++) {
                    const int j = ni >> 1, h = (ni & 1) * 2;
                    mma_fp16(acc[mi][ni], a_f[mi], b_f[j][h], b_f[j][h + 1]);
                }
            }
        }
    }

    // ---- epilogue: direct float2 stores ----
    float* C = out + (size_t)(1 + view) * EMB_ELEMS;
    const int rbase = m0 + warpM * 64 + (lane >> 2);
    const int cbase = n0 + warpN * 32 + (lane & 3) * 2;
    #pragma unroll
    for (int mi = 0; mi < 4; mi++) {
        #pragma unroll
        for (int ni = 0; ni < 4; ni++) {
            const size_t r0 = (size_t)(rbase + mi * 16);
            const int cc = cbase + ni * 8;
            *reinterpret_cast<float2*>(&C[r0 * FDIM + cc]) =
                make_float2(acc[mi][ni][0], acc[mi][ni][1]);
            *reinterpret_cast<float2*>(&C[(r0 + 8) * FDIM + cc]) =
                make_float2(acc[mi][ni][2], acc[mi][ni][3]);
        }
    }
}

// ---------------------------------------------------------------------------
// Host launch
// Inputs: feature_emb, kp_W, W_triu, W_tril (all fp32)
// Output: [embs_flatten | view_1 | view_2], each 4096*4096 fp32.
// ---------------------------------------------------------------------------
extern "C" void kernel_launch(void* const* d_in, const int* in_sizes, int n_in,
                              void* d_out, int out_size)
{
    const float* femb   = (const float*)d_in[0];
    const float* kpW    = (const float*)d_in[1];
    const float* W_triu = (const float*)d_in[2];
    const float* W_tril = (const float*)d_in[3];
    float* out = (float*)d_out;

    // Prep: kp_pair + W conversion (one launch)
    prep_kernel<<<PREP_BLOCKS, 256>>>(femb, kpW, W_triu, W_tril);

    // GEMMs + embs_flatten copy, PDL-launched
    cudaFuncSetAttribute(view_gemm_kernel,
                         cudaFuncAttributeMaxDynamicSharedMemorySize, SMEM_GEMM);

    cudaLaunchConfig_t cfg = {};
    cfg.gridDim  = dim3(GEMM_BLOCKS + COPYG_BLOCKS, 1, 1);
    cfg.blockDim = dim3(256, 1, 1);
    cfg.dynamicSmemBytes = SMEM_GEMM;
    cfg.stream = 0;
    cudaLaunchAttribute attrs[1];
    attrs[0].id = cudaLaunchAttributeProgrammaticStreamSerialization;
    attrs[0].val.programmaticStreamSerializationAllowed = 1;
    cfg.attrs = attrs;
    cfg.numAttrs = 1;
    cudaLaunchKernelEx(&cfg, view_gemm_kernel, out, (const float*)femb);
}